// round 9
// baseline (speedup 1.0000x reference)
#include <cuda_runtime.h>
#include <cuda_bf16.h>

// Chamfer distance matrix, B=32, G=64, N=32, C=3.
// R9: occupancy push on the R8 structure (single-evaluation tile, s32-redux
// column mins, packed f32x2 over g2 pairs). Changes:
//  - __launch_bounds__(256,5): target <=51 regs -> 5 CTAs = 40 warps/SM.
//  - s2a/s2b merged into ONE interleaved smem array (single base pointer,
//    fewer addressing regs/IMADs); still two broadcast LDS.128 per (j,m).

#define NP 32

typedef unsigned long long u64;

static __device__ __forceinline__ u64 pack2(float lo, float hi) {
    u64 r; asm("mov.b64 %0, {%1, %2};" : "=l"(r) : "f"(lo), "f"(hi)); return r;
}
static __device__ __forceinline__ float2 unpack2(u64 v) {
    float2 f; asm("mov.b64 {%0, %1}, %2;" : "=f"(f.x), "=f"(f.y) : "l"(v)); return f;
}
static __device__ __forceinline__ u64 fma2(u64 a, u64 b, u64 c) {
    u64 d; asm("fma.rn.f32x2 %0, %1, %2, %3;" : "=l"(d) : "l"(a), "l"(b), "l"(c)); return d;
}
static __device__ __forceinline__ u64 add2(u64 a, u64 b) {
    u64 d; asm("add.rn.f32x2 %0, %1, %2;" : "=l"(d) : "l"(a), "l"(b)); return d;
}
// Warp-wide float min for non-negative floats via s32 redux on the bits.
static __device__ __forceinline__ float warp_min_pos(float v) {
    return __int_as_float(__reduce_min_sync(0xffffffffu, __float_as_int(v)));
}

__global__ __launch_bounds__(256, 5)
void chamfer_matrix_kernel(const float* __restrict__ x1,
                           const float* __restrict__ x2,
                           float* __restrict__ out)
{
    // Interleaved pair-packed x2 subset (this block's g2-half = 16 pairs):
    //   s2[(p*32+m)*2 + 0] = {a.x,b.x, a.y,b.y}
    //   s2[(p*32+m)*2 + 1] = {a.z,b.z, a.w,b.w}
    __shared__ ulonglong2 s2[16 * NP * 2];     // 16 KB

    const int blk  = blockIdx.x;        // b*64 + gp*2 + half
    const int b    = blk >> 6;
    const int gp   = (blk >> 1) & 31;   // g1 pair -> groups 2gp, 2gp+1
    const int half = blk & 1;           // g2 groups [half*32, half*32+32)
    const int tid  = threadIdx.x;

    // Stage this block's 1024 x2 points, pre-packed pairwise.
    const float* __restrict__ x2b = x2 + (size_t)(b * 64 + half * 32) * NP * 3;
    #pragma unroll
    for (int i = tid; i < 32 * NP; i += 256) {
        const float X = x2b[i * 3 + 0];
        const float Y = x2b[i * 3 + 1];
        const float Z = x2b[i * 3 + 2];
        const float W = fmaf(X, X, fmaf(Y, Y, Z * Z));
        const int g = i >> 5, m = i & 31;       // local group 0..31
        const int p = g >> 1, h = g & 1;        // local pair 0..15
        float* da = (float*)&s2[(p * NP + m) * 2 + 0];
        float* db = (float*)&s2[(p * NP + m) * 2 + 1];
        da[0 + h] = X;  da[2 + h] = Y;
        db[0 + h] = Z;  db[2 + h] = W;
    }

    const int wid  = tid >> 5;
    const int lane = tid & 31;

    // Lane-own x1 points (groups 2gp, 2gp+1) straight from gmem (L2-hot).
    const int g1A = b * 64 + 2 * gp;
    const float* __restrict__ pA = x1 + (size_t)(g1A * NP + lane) * 3;
    const float* __restrict__ pB = pA + (size_t)NP * 3;
    const float xA = pA[0], yA = pA[1], zA = pA[2];
    const float xB = pB[0], yB = pB[1], zB = pB[2];
    const float wAs = fmaf(xA, xA, fmaf(yA, yA, zA * zA));
    const float wBs = fmaf(xB, xB, fmaf(yB, yB, zB * zB));

    // Pre-scaled (-2x) splats; norm splats for the in-loop bias.
    const u64 pxA = pack2(-2.0f * xA, -2.0f * xA);
    const u64 pyA = pack2(-2.0f * yA, -2.0f * yA);
    const u64 pzA = pack2(-2.0f * zA, -2.0f * zA);
    const u64 pxB = pack2(-2.0f * xB, -2.0f * xB);
    const u64 pyB = pack2(-2.0f * yB, -2.0f * yB);
    const u64 pzB = pack2(-2.0f * zB, -2.0f * zB);
    const u64 wA  = pack2(wAs, wAs);
    const u64 wB  = pack2(wBs, wBs);

    __syncthreads();

    const float FLTMAX = 3.402823466e+38f;
    float m1A0[2], m1A1[2], m1B0[2], m1B1[2];   // dir-1 row mins (lane = n)
    float sA0[2],  sA1[2],  sB0[2],  sB1[2];    // dir-2 colmin sums (uniform)
    #pragma unroll
    for (int j = 0; j < 2; j++) {
        m1A0[j] = m1A1[j] = m1B0[j] = m1B1[j] = FLTMAX;
        sA0[j] = sA1[j] = sB0[j] = sB1[j] = 0.0f;
    }

    // Single base pointer for this warp's 2 g2-pairs.
    const ulonglong2* __restrict__ q2 = &s2[wid * 2 * NP * 2];

    #pragma unroll 4
    for (int m = 0; m < NP; m++) {
        #pragma unroll
        for (int j = 0; j < 2; j++) {
            const ulonglong2 va = q2[(j * NP + m) * 2 + 0];   // {ax,bx, ay,by}
            const ulonglong2 vb = q2[(j * NP + m) * 2 + 1];   // {az,bz, aw,bw}
            // Full distance d[n][m] (>= 0), both g2 groups of the pair:
            const u64 dA = fma2(pxA, va.x, fma2(pyA, va.y, fma2(pzA, vb.x, add2(vb.y, wA))));
            const u64 dB = fma2(pxB, va.x, fma2(pyB, va.y, fma2(pzB, vb.x, add2(vb.y, wB))));
            const float2 fA = unpack2(dA);
            const float2 fB = unpack2(dB);
            // dir-1: lane-local running min over m.
            m1A0[j] = fminf(m1A0[j], fA.x);  m1A1[j] = fminf(m1A1[j], fA.y);
            m1B0[j] = fminf(m1B0[j], fB.x);  m1B1[j] = fminf(m1B1[j], fB.y);
            // dir-2: exact warp-wide min over n (s32 redux on bits), sum over m.
            sA0[j] += warp_min_pos(fA.x);    sA1[j] += warp_min_pos(fA.y);
            sB0[j] += warp_min_pos(fB.x);    sB1[j] += warp_min_pos(fB.y);
        }
    }

    // Epilogue: packed butterfly-sum of the dir-1 mins, add dir-2 sums.
    #pragma unroll
    for (int j = 0; j < 2; j++) {
        u64 vA = pack2(m1A0[j], m1A1[j]);
        u64 vB = pack2(m1B0[j], m1B1[j]);
        #pragma unroll
        for (int o = 16; o; o >>= 1) {
            vA = add2(vA, __shfl_xor_sync(0xffffffffu, vA, o));
            vB = add2(vB, __shfl_xor_sync(0xffffffffu, vB, o));
        }
        if (lane == 0) {
            const float2 rA = unpack2(vA);
            const float2 rB = unpack2(vB);
            const int g2 = half * 32 + (wid * 2 + j) * 2;
            out[(size_t)g1A * 64 + g2]           = (rA.x + sA0[j]) * (1.0f / 32.0f);
            out[(size_t)g1A * 64 + g2 + 1]       = (rA.y + sA1[j]) * (1.0f / 32.0f);
            out[(size_t)(g1A + 1) * 64 + g2]     = (rB.x + sB0[j]) * (1.0f / 32.0f);
            out[(size_t)(g1A + 1) * 64 + g2 + 1] = (rB.y + sB1[j]) * (1.0f / 32.0f);
        }
    }
}

extern "C" void kernel_launch(void* const* d_in, const int* in_sizes, int n_in,
                              void* d_out, int out_size) {
    const float* x1  = (const float*)d_in[0];  // xyz1_matrix [32,64,32,3]
    const float* x2  = (const float*)d_in[1];  // xyz2_matrix [32,64,32,3]
    float*       out = (float*)d_out;          // [32,64,64]
    chamfer_matrix_kernel<<<32 * 64, 256>>>(x1, x2, out);
}

// round 10
// speedup vs baseline: 1.1308x; 1.1308x over previous
#include <cuda_runtime.h>
#include <cuda_bf16.h>

// Chamfer distance matrix, B=32, G=64, N=32, C=3.
// R10: tail-wave fix on the R8 structure (single-evaluation tile, s32-redux
// column mins, packed f32x2 over g2 pairs, (256,4) = 32 warps/SM).
// Warp tile = 1 g2-pair (j=1); block = (b, g1-pair, g2-QUARTER); grid 4096.
// Per-combo issue cost is j-invariant, but waves go 3.37 -> 6.74, cutting
// the scheduler tail from 18.8% to 3.9%. Registers relax naturally (~55),
// avoiding the R9 reg-squeeze codegen pathology.

#define NP 32

typedef unsigned long long u64;

static __device__ __forceinline__ u64 pack2(float lo, float hi) {
    u64 r; asm("mov.b64 %0, {%1, %2};" : "=l"(r) : "f"(lo), "f"(hi)); return r;
}
static __device__ __forceinline__ float2 unpack2(u64 v) {
    float2 f; asm("mov.b64 {%0, %1}, %2;" : "=f"(f.x), "=f"(f.y) : "l"(v)); return f;
}
static __device__ __forceinline__ u64 fma2(u64 a, u64 b, u64 c) {
    u64 d; asm("fma.rn.f32x2 %0, %1, %2, %3;" : "=l"(d) : "l"(a), "l"(b), "l"(c)); return d;
}
static __device__ __forceinline__ u64 add2(u64 a, u64 b) {
    u64 d; asm("add.rn.f32x2 %0, %1, %2;" : "=l"(d) : "l"(a), "l"(b)); return d;
}
// Warp-wide float min for non-negative floats via s32 redux on the bits.
static __device__ __forceinline__ float warp_min_pos(float v) {
    return __int_as_float(__reduce_min_sync(0xffffffffu, __float_as_int(v)));
}

__global__ __launch_bounds__(256, 4)
void chamfer_matrix_kernel(const float* __restrict__ x1,
                           const float* __restrict__ x2,
                           float* __restrict__ out)
{
    // Pair-packed x2 subset (this block's g2-quarter = 8 pairs):
    //   s2a[p*32+m] = {a.x,b.x, a.y,b.y}; s2b[p*32+m] = {a.z,b.z, a.w,b.w}
    __shared__ ulonglong2 s2a[8 * NP];      // 4 KB
    __shared__ ulonglong2 s2b[8 * NP];      // 4 KB

    const int blk = blockIdx.x;         // ((b*32 + gp)*4 + q)
    const int b   = blk >> 7;
    const int gp  = (blk >> 2) & 31;    // g1 pair -> groups 2gp, 2gp+1
    const int q   = blk & 3;            // g2 quarter -> groups [q*16, q*16+16)
    const int tid = threadIdx.x;

    // Stage this block's 512 x2 points, pre-packed pairwise.
    const float* __restrict__ x2b = x2 + (size_t)(b * 64 + q * 16) * NP * 3;
    #pragma unroll
    for (int i = tid; i < 16 * NP; i += 256) {
        const float X = x2b[i * 3 + 0];
        const float Y = x2b[i * 3 + 1];
        const float Z = x2b[i * 3 + 2];
        const float W = fmaf(X, X, fmaf(Y, Y, Z * Z));
        const int g = i >> 5, m = i & 31;       // local group 0..15
        const int p = g >> 1, h = g & 1;        // local pair 0..7
        float* da = (float*)&s2a[p * NP + m];
        float* db = (float*)&s2b[p * NP + m];
        da[0 + h] = X;  da[2 + h] = Y;
        db[0 + h] = Z;  db[2 + h] = W;
    }

    const int wid  = tid >> 5;
    const int lane = tid & 31;

    // Lane-own x1 points (groups 2gp, 2gp+1) straight from gmem (L2-hot).
    const int g1A = b * 64 + 2 * gp;
    const float* __restrict__ pA = x1 + (size_t)(g1A * NP + lane) * 3;
    const float* __restrict__ pB = pA + (size_t)NP * 3;
    const float xA = pA[0], yA = pA[1], zA = pA[2];
    const float xB = pB[0], yB = pB[1], zB = pB[2];
    const float wAs = fmaf(xA, xA, fmaf(yA, yA, zA * zA));
    const float wBs = fmaf(xB, xB, fmaf(yB, yB, zB * zB));

    // Pre-scaled (-2x) splats; norm splats for the in-loop bias.
    const u64 pxA = pack2(-2.0f * xA, -2.0f * xA);
    const u64 pyA = pack2(-2.0f * yA, -2.0f * yA);
    const u64 pzA = pack2(-2.0f * zA, -2.0f * zA);
    const u64 pxB = pack2(-2.0f * xB, -2.0f * xB);
    const u64 pyB = pack2(-2.0f * yB, -2.0f * yB);
    const u64 pzB = pack2(-2.0f * zB, -2.0f * zB);
    const u64 wA  = pack2(wAs, wAs);
    const u64 wB  = pack2(wBs, wBs);

    __syncthreads();

    const float FLTMAX = 3.402823466e+38f;
    float m1A0 = FLTMAX, m1A1 = FLTMAX, m1B0 = FLTMAX, m1B1 = FLTMAX;
    float sA0 = 0.0f, sA1 = 0.0f, sB0 = 0.0f, sB1 = 0.0f;

    // This warp's single g2-pair.
    const ulonglong2* __restrict__ q2a = &s2a[wid * NP];
    const ulonglong2* __restrict__ q2b = &s2b[wid * NP];

    #pragma unroll 4
    for (int m = 0; m < NP; m++) {
        const ulonglong2 va = q2a[m];   // {ax,bx, ay,by}  broadcast LDS.128
        const ulonglong2 vb = q2b[m];   // {az,bz, aw,bw}  broadcast LDS.128
        // Full distance d[n][m] (>= 0), both g2 groups of the pair:
        const u64 dA = fma2(pxA, va.x, fma2(pyA, va.y, fma2(pzA, vb.x, add2(vb.y, wA))));
        const u64 dB = fma2(pxB, va.x, fma2(pyB, va.y, fma2(pzB, vb.x, add2(vb.y, wB))));
        const float2 fA = unpack2(dA);
        const float2 fB = unpack2(dB);
        // dir-1: lane-local running min over m.
        m1A0 = fminf(m1A0, fA.x);  m1A1 = fminf(m1A1, fA.y);
        m1B0 = fminf(m1B0, fB.x);  m1B1 = fminf(m1B1, fB.y);
        // dir-2: exact warp-wide min over n (s32 redux on bits), sum over m.
        sA0 += warp_min_pos(fA.x);  sA1 += warp_min_pos(fA.y);
        sB0 += warp_min_pos(fB.x);  sB1 += warp_min_pos(fB.y);
    }

    // Epilogue: packed butterfly-sum of the dir-1 mins, add dir-2 sums.
    u64 vA = pack2(m1A0, m1A1);
    u64 vB = pack2(m1B0, m1B1);
    #pragma unroll
    for (int o = 16; o; o >>= 1) {
        vA = add2(vA, __shfl_xor_sync(0xffffffffu, vA, o));
        vB = add2(vB, __shfl_xor_sync(0xffffffffu, vB, o));
    }
    if (lane == 0) {
        const float2 rA = unpack2(vA);
        const float2 rB = unpack2(vB);
        const int g2 = q * 16 + wid * 2;
        out[(size_t)g1A * 64 + g2]           = (rA.x + sA0) * (1.0f / 32.0f);
        out[(size_t)g1A * 64 + g2 + 1]       = (rA.y + sA1) * (1.0f / 32.0f);
        out[(size_t)(g1A + 1) * 64 + g2]     = (rB.x + sB0) * (1.0f / 32.0f);
        out[(size_t)(g1A + 1) * 64 + g2 + 1] = (rB.y + sB1) * (1.0f / 32.0f);
    }
}

extern "C" void kernel_launch(void* const* d_in, const int* in_sizes, int n_in,
                              void* d_out, int out_size) {
    const float* x1  = (const float*)d_in[0];  // xyz1_matrix [32,64,32,3]
    const float* x2  = (const float*)d_in[1];  // xyz2_matrix [32,64,32,3]
    float*       out = (float*)d_out;          // [32,64,64]
    chamfer_matrix_kernel<<<32 * 32 * 4, 256>>>(x1, x2, out);
}